// round 11
// baseline (speedup 1.0000x reference)
#include <cuda_runtime.h>

// ConvEnhanced: 2x2 valid conv + ReLU -> channel 0.
// Quantum circuit collapses analytically: RZ layers are diagonal phases,
// CNOT layers are permutations; Z0 after two CNOT layers = Z0*Z1*Z3 on the
// RX product state => qval = cos(p00)*cos(p01)*cos(p11). qparams unused.
// Channel 1 = qval replicated over each 2x2 patch.
//
// x: [64,1,257,257] f32; out: [64,2,256,256] f32.
//
// R11: single-wave persistent grid. 2048 blocks x 128 threads = 262,144
// resident threads (<= 2368-block concurrency at 16 blocks/SM), each thread
// processes exactly 4 patches via grid-stride loop. Eliminates the ~2.5
// wave transitions (~2360 cyc each) that the composed T_chip model says
// dominate the previous 8192-block launches. No smem, no barriers.

#define IN_HW   257
#define OUT_HW  256
#define HP      128
#define BATCH   64
#define N_PATCH   (BATCH * HP * HP)     // 1,048,576
#define N_BLOCKS  2048
#define N_THREADS 128
#define STRIDE    (N_BLOCKS * N_THREADS)  // 262,144
#define ITERS     (N_PATCH / STRIDE)      // 4, exact

__global__ __launch_bounds__(N_THREADS)
void conv_enhanced_kernel(const float* __restrict__ x,
                          const float* __restrict__ w,
                          const float* __restrict__ bias,
                          float* __restrict__ out)
{
    const float w00 = __ldg(w + 0);
    const float w01 = __ldg(w + 1);
    const float w10 = __ldg(w + 2);
    const float w11 = __ldg(w + 3);
    const float bb  = __ldg(bias);

    int idx = blockIdx.x * N_THREADS + threadIdx.x;

#pragma unroll 1
    for (int k = 0; k < ITERS; ++k, idx += STRIDE) {
        const int pw = idx & (HP - 1);
        const int ph = (idx >> 7) & (HP - 1);
        const int b  = idx >> 14;

        const int r = ph * 2;
        const int c = pw * 2;
        const float* row0 = x + (size_t)b * (IN_HW * IN_HW) + r * IN_HW + c;
        const float* row1 = row0 + IN_HW;
        const float* row2 = row1 + IN_HW;

        const float x00 = __ldg(row0 + 0), x01 = __ldg(row0 + 1), x02 = __ldg(row0 + 2);
        const float x10 = __ldg(row1 + 0), x11 = __ldg(row1 + 1), x12 = __ldg(row1 + 2);
        const float x20 = __ldg(row2 + 0), x21 = __ldg(row2 + 1), x22 = __ldg(row2 + 2);

        const float p00 = fmaxf(fmaf(w00, x00, fmaf(w01, x01, fmaf(w10, x10, fmaf(w11, x11, bb)))), 0.f);
        const float p01 = fmaxf(fmaf(w00, x01, fmaf(w01, x02, fmaf(w10, x11, fmaf(w11, x12, bb)))), 0.f);
        const float p10 = fmaxf(fmaf(w00, x10, fmaf(w01, x11, fmaf(w10, x20, fmaf(w11, x21, bb)))), 0.f);
        const float p11 = fmaxf(fmaf(w00, x11, fmaf(w01, x12, fmaf(w10, x21, fmaf(w11, x22, bb)))), 0.f);

        const float q = __cosf(p00) * __cosf(p01) * __cosf(p11);

        float* ob = out + (size_t)b * (2 * OUT_HW * OUT_HW);
        const int o0 = r * OUT_HW + c;               // c even -> 8B aligned

        *reinterpret_cast<float2*>(ob + o0)          = make_float2(p00, p01);
        *reinterpret_cast<float2*>(ob + o0 + OUT_HW) = make_float2(p10, p11);

        float* ob1 = ob + OUT_HW * OUT_HW;
        const float2 qq = make_float2(q, q);
        *reinterpret_cast<float2*>(ob1 + o0)          = qq;
        *reinterpret_cast<float2*>(ob1 + o0 + OUT_HW) = qq;
    }
}

extern "C" void kernel_launch(void* const* d_in, const int* in_sizes, int n_in,
                              void* d_out, int out_size)
{
    const float* x      = (const float*)d_in[0];
    const float* conv_w = (const float*)d_in[1];
    const float* conv_b = (const float*)d_in[2];
    // d_in[3] = qparams: provably unused
    float* out = (float*)d_out;

    conv_enhanced_kernel<<<N_BLOCKS, N_THREADS>>>(x, conv_w, conv_b, out);
}

// round 12
// speedup vs baseline: 1.0213x; 1.0213x over previous
#include <cuda_runtime.h>

// ConvEnhanced: 2x2 valid conv + ReLU -> channel 0.
//
// The "quantum" 4-qubit circuit collapses analytically:
//   - RZ layers are diagonal phase multiplications (|amp|^2 invariant)
//   - CNOT layers are basis permutations
//   - measuring Z0 after two 'full' CNOT layers == measuring Z0*Z1*Z3 on the
//     RX product state  =>  qval = cos(p00)*cos(p01)*cos(p11)
//   - qparams are provably irrelevant to the output.
// Channel 1 = qval replicated over each 2x2 patch.
//
// x: [64,1,257,257] f32; out: [64,2,256,256] f32.
//
// Final configuration (best of 7 structural variants benchmarked):
//   - 1 thread per 2x2 patch, 1,048,576 threads, 256-thread blocks
//     (max parallelism won every comparison; smem/TMA/one-wave all slower
//      or neutral)
//   - scalar 8B-stride loads (18 L1 wavefronts/warp-iter -- measured better
//     than every vectorized alternative given the odd 257-row pitch)
//   - float2 stores (c is even -> 8B aligned, dense 128B lines per warp)
//   - __cosf fast path: abs err ~1e-5 vs 1e-3 threshold (measured
//     rel_err 9.9e-8)
// Measured: ncu ~9.8-9.9us; harness 10.69-10.72us (harness replay floor --
// all kernel variants with ncu <= 10.3us read identically).

#define IN_HW   257
#define OUT_HW  256
#define HP      128
#define BATCH   64
#define N_PATCH (BATCH * HP * HP)   // 1,048,576

__global__ __launch_bounds__(256)
void conv_enhanced_kernel(const float* __restrict__ x,
                          const float* __restrict__ w,
                          const float* __restrict__ bias,
                          float* __restrict__ out)
{
    const int idx = blockIdx.x * blockDim.x + threadIdx.x;   // exact grid
    const int pw = idx & (HP - 1);
    const int ph = (idx >> 7) & (HP - 1);
    const int b  = idx >> 14;

    const float w00 = __ldg(w + 0);
    const float w01 = __ldg(w + 1);
    const float w10 = __ldg(w + 2);
    const float w11 = __ldg(w + 3);
    const float bb  = __ldg(bias);

    const int r = ph * 2;
    const int c = pw * 2;
    const float* row0 = x + (size_t)b * (IN_HW * IN_HW) + r * IN_HW + c;
    const float* row1 = row0 + IN_HW;
    const float* row2 = row1 + IN_HW;

    const float x00 = __ldg(row0 + 0), x01 = __ldg(row0 + 1), x02 = __ldg(row0 + 2);
    const float x10 = __ldg(row1 + 0), x11 = __ldg(row1 + 1), x12 = __ldg(row1 + 2);
    const float x20 = __ldg(row2 + 0), x21 = __ldg(row2 + 1), x22 = __ldg(row2 + 2);

    const float p00 = fmaxf(fmaf(w00, x00, fmaf(w01, x01, fmaf(w10, x10, fmaf(w11, x11, bb)))), 0.f);
    const float p01 = fmaxf(fmaf(w00, x01, fmaf(w01, x02, fmaf(w10, x11, fmaf(w11, x12, bb)))), 0.f);
    const float p10 = fmaxf(fmaf(w00, x10, fmaf(w01, x11, fmaf(w10, x20, fmaf(w11, x21, bb)))), 0.f);
    const float p11 = fmaxf(fmaf(w00, x11, fmaf(w01, x12, fmaf(w10, x21, fmaf(w11, x22, bb)))), 0.f);

    const float q = __cosf(p00) * __cosf(p01) * __cosf(p11);

    float* ob = out + (size_t)b * (2 * OUT_HW * OUT_HW);
    const int o0 = r * OUT_HW + c;                 // c even -> 8B aligned

    // channel 0: conv + relu
    *reinterpret_cast<float2*>(ob + o0)          = make_float2(p00, p01);
    *reinterpret_cast<float2*>(ob + o0 + OUT_HW) = make_float2(p10, p11);
    // channel 1: qmap replicated 2x2
    float* ob1 = ob + OUT_HW * OUT_HW;
    const float2 qq = make_float2(q, q);
    *reinterpret_cast<float2*>(ob1 + o0)          = qq;
    *reinterpret_cast<float2*>(ob1 + o0 + OUT_HW) = qq;
}

extern "C" void kernel_launch(void* const* d_in, const int* in_sizes, int n_in,
                              void* d_out, int out_size)
{
    const float* x      = (const float*)d_in[0];
    const float* conv_w = (const float*)d_in[1];
    const float* conv_b = (const float*)d_in[2];
    // d_in[3] = qparams: provably unused
    float* out = (float*)d_out;

    const int threads = 256;
    const int blocks  = N_PATCH / threads;   // 4096
    conv_enhanced_kernel<<<blocks, threads>>>(x, conv_w, conv_b, out);
}